// round 1
// baseline (speedup 1.0000x reference)
#include <cuda_runtime.h>
#include <math.h>

#define N_USER   100000
#define N_ITEM   50000
#define N_NODES_ (N_USER + N_ITEM)   // 150000
#define NNZ_     4800000
#define EMB      64
#define N_LAYERS 3
#define BATCH_   16384
#define EPS_     1e-12f
#define NEG_SLOPE 0.2f

// ---------------- scratch (device globals: allocation-free rule) -------------
__device__ float g_ego [N_NODES_ * EMB];        // 38.4 MB  (current layer input, unnormalized)
__device__ float g_side[N_NODES_ * EMB];        // 38.4 MB  (A_hat @ ego accumulator)
__device__ float g_all [N_NODES_ * 4 * EMB];    // 153.6 MB (concat of 4 embedding blocks)

// ---------------- init: ego = concat(user_emb, item_emb); all[:,0:64] = ego --
__global__ void init_kernel(const float* __restrict__ ue, const float* __restrict__ ie) {
    int idx = blockIdx.x * blockDim.x + threadIdx.x;      // float4 index
    const int total = N_NODES_ * EMB / 4;                 // 2.4M (exact multiple of 256)
    if (idx >= total) return;
    int node = idx >> 4;          // /16 float4 per row
    int c4   = idx & 15;
    float4 v;
    if (node < N_USER) v = __ldg((const float4*)ue + node * 16 + c4);
    else               v = __ldg((const float4*)ie + (node - N_USER) * 16 + c4);
    ((float4*)g_ego)[idx] = v;
    ((float4*)g_all)[node * 64 + c4] = v;   // row stride 256 floats = 64 float4
}

// ---------------- zero the scatter accumulator -------------------------------
__global__ void zero_kernel() {
    int idx = blockIdx.x * blockDim.x + threadIdx.x;
    ((float4*)g_side)[idx] = make_float4(0.f, 0.f, 0.f, 0.f);
}

// ---------------- SpMM: side[r] += val * ego[c], 16 threads per edge ----------
__global__ void spmm_kernel(const int* __restrict__ rows,
                            const int* __restrict__ cols,
                            const float* __restrict__ vals) {
    int t = blockIdx.x * blockDim.x + threadIdx.x;
    int e = t >> 4;
    if (e >= NNZ_) return;
    int l = t & 15;
    int c    = __ldg(&cols[e]);
    int r    = __ldg(&rows[e]);
    float v  = __ldg(&vals[e]);
    float4 g = __ldg((const float4*)g_ego + c * 16 + l);
    float4 m = make_float4(g.x * v, g.y * v, g.z * v, g.w * v);
    float* dst = g_side + ((size_t)r * EMB + l * 4);
    asm volatile("red.global.add.v4.f32 [%0], {%1,%2,%3,%4};"
                 :: "l"(dst), "f"(m.x), "f"(m.y), "f"(m.z), "f"(m.w) : "memory");
}

// ---------------- fused dense transform + leaky_relu + L2-normalize ----------
// ego_new = leaky( side@Wgc + bgc + (ego*side)@Wbi + bbi )
// g_ego <- ego_new ; g_all[:, (layer+1)*64 : ] <- ego_new / max(norm, eps)
// Block: 256 threads, 64-row tile, thread(ty,tx) computes rows ty*4..+3, cols tx*4..+3
__global__ void transform_kernel(const float* __restrict__ Wgc,
                                 const float* __restrict__ bgc,
                                 const float* __restrict__ Wbi,
                                 const float* __restrict__ bbi,
                                 int layer) {
    extern __shared__ float sh[];
    float* Ssh = sh;                    // [64][65]
    float* Psh = Ssh + 64 * 65;         // [64][65]
    float* Wg  = Psh + 64 * 65;         // [64][64]
    float* Wb  = Wg  + 64 * 64;         // [64][64]
    float* bs  = Wb  + 64 * 64;         // [64]

    const int tid = threadIdx.x;
    const int rowBase = blockIdx.x * 64;

    // stage weights (4096 floats each = 1024 float4)
    for (int i = tid; i < 1024; i += 256) {
        ((float4*)Wg)[i] = __ldg((const float4*)Wgc + i);
        ((float4*)Wb)[i] = __ldg((const float4*)Wbi + i);
    }
    if (tid < 64) bs[tid] = __ldg(bgc + tid) + __ldg(bbi + tid);

    // stage side & ego*side tiles (64 rows x 16 float4)
    for (int i = tid; i < 1024; i += 256) {
        int r  = i >> 4;
        int c4 = i & 15;
        int gr = rowBase + r;
        float4 s = make_float4(0.f, 0.f, 0.f, 0.f);
        float4 e = make_float4(0.f, 0.f, 0.f, 0.f);
        if (gr < N_NODES_) {
            s = ((const float4*)g_side)[gr * 16 + c4];
            e = ((const float4*)g_ego )[gr * 16 + c4];
        }
        float* sp = Ssh + r * 65 + c4 * 4;
        sp[0] = s.x; sp[1] = s.y; sp[2] = s.z; sp[3] = s.w;
        float* pp = Psh + r * 65 + c4 * 4;
        pp[0] = e.x * s.x; pp[1] = e.y * s.y; pp[2] = e.z * s.z; pp[3] = e.w * s.w;
    }
    __syncthreads();

    const int tx = tid & 15;
    const int ty = tid >> 4;
    float acc[4][4];
#pragma unroll
    for (int i = 0; i < 4; i++)
#pragma unroll
        for (int j = 0; j < 4; j++) acc[i][j] = 0.f;

#pragma unroll 8
    for (int k = 0; k < 64; k++) {
        float4 bg = *(const float4*)&Wg[k * 64 + tx * 4];
        float4 bb = *(const float4*)&Wb[k * 64 + tx * 4];
        float as[4], ap[4];
#pragma unroll
        for (int i = 0; i < 4; i++) {
            as[i] = Ssh[(ty * 4 + i) * 65 + k];   // broadcast across tx lanes
            ap[i] = Psh[(ty * 4 + i) * 65 + k];
        }
#pragma unroll
        for (int i = 0; i < 4; i++) {
            acc[i][0] += as[i] * bg.x + ap[i] * bb.x;
            acc[i][1] += as[i] * bg.y + ap[i] * bb.y;
            acc[i][2] += as[i] * bg.z + ap[i] * bb.z;
            acc[i][3] += as[i] * bg.w + ap[i] * bb.w;
        }
    }

    // epilogue: bias + leaky, row-norm reduction across 16 tx lanes
    const int colBase = tx * 4;
    float v[4][4];
    float sq[4];
#pragma unroll
    for (int i = 0; i < 4; i++) {
        float x0 = acc[i][0] + bs[colBase + 0];
        float x1 = acc[i][1] + bs[colBase + 1];
        float x2 = acc[i][2] + bs[colBase + 2];
        float x3 = acc[i][3] + bs[colBase + 3];
        x0 = fmaxf(x0, NEG_SLOPE * x0);
        x1 = fmaxf(x1, NEG_SLOPE * x1);
        x2 = fmaxf(x2, NEG_SLOPE * x2);
        x3 = fmaxf(x3, NEG_SLOPE * x3);
        v[i][0] = x0; v[i][1] = x1; v[i][2] = x2; v[i][3] = x3;
        float s = x0 * x0 + x1 * x1 + x2 * x2 + x3 * x3;
#pragma unroll
        for (int off = 1; off < 16; off <<= 1)
            s += __shfl_xor_sync(0xffffffffu, s, off);
        sq[i] = s;
    }

#pragma unroll
    for (int i = 0; i < 4; i++) {
        int gr = rowBase + ty * 4 + i;
        if (gr >= N_NODES_) continue;
        float inv = 1.0f / fmaxf(sqrtf(sq[i]), EPS_);
        float4 raw = make_float4(v[i][0], v[i][1], v[i][2], v[i][3]);
        float4 nrm = make_float4(v[i][0] * inv, v[i][1] * inv, v[i][2] * inv, v[i][3] * inv);
        *(float4*)&g_ego[(size_t)gr * EMB + colBase] = raw;
        *(float4*)&g_all[(size_t)gr * 256 + (layer + 1) * 64 + colBase] = nrm;
    }
}

// ---------------- GMF head: sigmoid((u*i)@W_out + b_out) ---------------------
__global__ void head_kernel(const int* __restrict__ uidx,
                            const int* __restrict__ iidx,
                            const float* __restrict__ Wout,
                            const float* __restrict__ bout,
                            float* __restrict__ out) {
    int gw = (blockIdx.x * blockDim.x + threadIdx.x) >> 5;
    if (gw >= BATCH_) return;
    int lane = threadIdx.x & 31;
    int u  = __ldg(&uidx[gw]);
    int it = __ldg(&iidx[gw]) + N_USER;
    const float4* ur = (const float4*)(g_all + (size_t)u  * 256);
    const float4* ir = (const float4*)(g_all + (size_t)it * 256);
    const float4* w4 = (const float4*)Wout;
    float acc = 0.f;
#pragma unroll
    for (int q = 0; q < 2; q++) {
        int c = lane + q * 32;
        float4 a = ur[c];
        float4 b = ir[c];
        float4 w = __ldg(&w4[c]);
        acc += a.x * b.x * w.x + a.y * b.y * w.y + a.z * b.z * w.z + a.w * b.w * w.w;
    }
#pragma unroll
    for (int off = 16; off; off >>= 1)
        acc += __shfl_xor_sync(0xffffffffu, acc, off);
    if (lane == 0) {
        float z = acc + __ldg(bout);
        out[gw] = 1.0f / (1.0f + expf(-z));
    }
}

// ---------------- launch ------------------------------------------------------
extern "C" void kernel_launch(void* const* d_in, const int* in_sizes, int n_in,
                              void* d_out, int out_size) {
    const int*   user_idx = (const int*)  d_in[0];
    const int*   item_idx = (const int*)  d_in[1];
    const int*   adj_rows = (const int*)  d_in[2];
    const int*   adj_cols = (const int*)  d_in[3];
    const float* adj_vals = (const float*)d_in[4];
    const float* user_emb = (const float*)d_in[5];
    const float* item_emb = (const float*)d_in[6];
    const float* W_gc     = (const float*)d_in[7];
    const float* b_gc     = (const float*)d_in[8];
    const float* W_bi     = (const float*)d_in[9];
    const float* b_bi     = (const float*)d_in[10];
    const float* W_out    = (const float*)d_in[11];
    const float* b_out    = (const float*)d_in[12];
    float* out = (float*)d_out;

    const int smem = (64 * 65 * 2 + 64 * 64 * 2 + 64) * (int)sizeof(float);  // 66304 B
    cudaFuncSetAttribute(transform_kernel,
                         cudaFuncAttributeMaxDynamicSharedMemorySize, smem);

    const int vec_blocks = (N_NODES_ * EMB / 4) / 256;   // 9375 exactly
    init_kernel<<<vec_blocks, 256>>>(user_emb, item_emb);

    const int spmm_blocks = (NNZ_ * 16 + 255) / 256;     // 300000
    const int tile_blocks = (N_NODES_ + 63) / 64;        // 2344

    for (int l = 0; l < N_LAYERS; l++) {
        zero_kernel<<<vec_blocks, 256>>>();
        spmm_kernel<<<spmm_blocks, 256>>>(adj_rows, adj_cols, adj_vals);
        transform_kernel<<<tile_blocks, 256, smem>>>(W_gc + l * EMB * EMB,
                                                     b_gc + l * EMB,
                                                     W_bi + l * EMB * EMB,
                                                     b_bi + l * EMB,
                                                     l);
    }

    head_kernel<<<(BATCH_ * 32 + 255) / 256, 256>>>(user_idx, item_idx, W_out, b_out, out);
}